// round 2
// baseline (speedup 1.0000x reference)
#include <cuda_runtime.h>
#include <cstddef>

#define N_NODES 50000
#define D 128
#define E_EDGES 800000

// Scratch (no allocations allowed in kernel_launch)
__device__ float d_s[(size_t)N_NODES * D];   // segment-sum accumulator
__device__ float d_h[(size_t)N_NODES * D];   // layer-1 output
__device__ float d_inv[N_NODES];             // 1/max(cnt,1)
__device__ int   d_cnt[N_NODES];
__device__ float d_wt1[256 * 128];           // combined [Wl1;Wr1] transposed: wt[k][j]
__device__ float d_wt2[256 * 128];

// ---------------------------------------------------------------------------
__global__ void zero_s_cnt_kernel(int zero_cnt) {
    int stride = gridDim.x * blockDim.x;
    int i0 = blockIdx.x * blockDim.x + threadIdx.x;
    for (size_t i = i0; i < (size_t)N_NODES * D; i += stride) d_s[i] = 0.0f;
    if (zero_cnt) {
        for (int i = i0; i < N_NODES; i += stride) d_cnt[i] = 0;
    }
}

__global__ void count_kernel(const int* __restrict__ dst) {
    int stride = gridDim.x * blockDim.x;
    for (int e = blockIdx.x * blockDim.x + threadIdx.x; e < E_EDGES; e += stride) {
        atomicAdd(&d_cnt[dst[e]], 1);
    }
}

// Build inv counts + transposed combined weights wt[k*128+j]:
//   k <  128 : Wl[j*128 + k]
//   k >= 128 : Wr[j*128 + (k-128)]
__global__ void prep_kernel(const float* __restrict__ Wl1, const float* __restrict__ Wr1,
                            const float* __restrict__ Wl2, const float* __restrict__ Wr2) {
    int stride = gridDim.x * blockDim.x;
    int i0 = blockIdx.x * blockDim.x + threadIdx.x;
    for (int i = i0; i < 256 * 128; i += stride) {
        int k = i >> 7;
        int j = i & 127;
        if (k < 128) {
            d_wt1[i] = Wl1[j * 128 + k];
            d_wt2[i] = Wl2[j * 128 + k];
        } else {
            d_wt1[i] = Wr1[j * 128 + (k - 128)];
            d_wt2[i] = Wr2[j * 128 + (k - 128)];
        }
    }
    for (int n = i0; n < N_NODES; n += stride) {
        d_inv[n] = 1.0f / fmaxf((float)d_cnt[n], 1.0f);
    }
}

// One warp per edge: lane l moves 4 floats via vector reduction into d_s[dst].
// layer==0 reads from x (param); layer==1 reads from d_h (device symbol).
__global__ void __launch_bounds__(256) scatter_kernel(const float* __restrict__ x,
                                                      const int* __restrict__ src,
                                                      const int* __restrict__ dst,
                                                      int layer) {
    const float* __restrict__ xin = (layer == 0) ? x : d_h;
    int gid = blockIdx.x * blockDim.x + threadIdx.x;
    int e = gid >> 5;
    if (e >= E_EDGES) return;
    int lane = gid & 31;
    int sv = __ldg(src + e);
    int dv = __ldg(dst + e);
    float4 v = *(const float4*)(xin + (size_t)sv * D + lane * 4);
    float* p = d_s + (size_t)dv * D + lane * 4;
    asm volatile("red.global.add.v4.f32 [%0], {%1, %2, %3, %4};"
                 :: "l"(p), "f"(v.x), "f"(v.y), "f"(v.z), "f"(v.w) : "memory");
}

// Fused: out[n][j] = sum_{k<128} (s[n][k]*inv[n]) * wt[k][j]
//                  + sum_{k>=128} xin[n][k-128]   * wt[k][j]   + bias[j]
// Tiled SGEMM: BM=64, BN=128, BK=32, 256 threads, 8x4 per-thread microtile.
// layer==0: A-right-half = x (param), output -> d_h, weights d_wt1
// layer==1: A-right-half = d_h,       output -> out (param), weights d_wt2
__global__ void __launch_bounds__(256) gemm_kernel(const float* __restrict__ x,
                                                   const float* __restrict__ bias,
                                                   float* __restrict__ outp,
                                                   int layer) {
    const float* __restrict__ wt  = (layer == 0) ? d_wt1 : d_wt2;
    const float* __restrict__ xin = (layer == 0) ? x : d_h;
    float* __restrict__ out       = (layer == 0) ? d_h : outp;

    __shared__ float As[32][68];    // [k][m], stride 68 keeps 16B alignment
    __shared__ float Bs[32][128];   // [k][j]

    int tid = threadIdx.x;
    int block_row0 = blockIdx.x * 64;
    int rowg = tid >> 5;    // 0..7  -> rows rowg*8 .. +7
    int colg = tid & 31;    // 0..31 -> cols colg*4 .. +3

    float acc[8][4];
#pragma unroll
    for (int i = 0; i < 8; i++)
#pragma unroll
        for (int j = 0; j < 4; j++) acc[i][j] = 0.0f;

    int la_row = tid >> 3;        // 0..31 (plus +32 second half)
    int la_k   = (tid & 7) * 4;   // 0,4,...,28

    for (int kt = 0; kt < 256; kt += 32) {
        // ---- load A tile (64 x 32) ----
#pragma unroll
        for (int i = 0; i < 2; i++) {
            int r = la_row + i * 32;
            int gr = block_row0 + r;
            int grc = (gr < N_NODES) ? gr : (N_NODES - 1);
            float4 v;
            if (kt < 128) {
                v = *(const float4*)(d_s + (size_t)grc * D + kt + la_k);
                float iv = d_inv[grc];
                v.x *= iv; v.y *= iv; v.z *= iv; v.w *= iv;
            } else {
                v = *(const float4*)(xin + (size_t)grc * D + (kt - 128) + la_k);
            }
            As[la_k + 0][r] = v.x;
            As[la_k + 1][r] = v.y;
            As[la_k + 2][r] = v.z;
            As[la_k + 3][r] = v.w;
        }
        // ---- load B tile (32 x 128) ----
#pragma unroll
        for (int t = 0; t < 4; t++) {
            int fidx = tid + t * 256;       // float4 index within 32x128 tile
            int k = fidx >> 5;
            int j = (fidx & 31) * 4;
            *(float4*)&Bs[k][j] = *(const float4*)(wt + (size_t)(kt + k) * 128 + j);
        }
        __syncthreads();

#pragma unroll
        for (int k = 0; k < 32; k++) {
            float4 a0 = *(const float4*)&As[k][rowg * 8];
            float4 a1 = *(const float4*)&As[k][rowg * 8 + 4];
            float4 b0 = *(const float4*)&Bs[k][colg * 4];
            float a[8] = {a0.x, a0.y, a0.z, a0.w, a1.x, a1.y, a1.z, a1.w};
            float b[4] = {b0.x, b0.y, b0.z, b0.w};
#pragma unroll
            for (int i = 0; i < 8; i++)
#pragma unroll
                for (int j = 0; j < 4; j++)
                    acc[i][j] += a[i] * b[j];
        }
        __syncthreads();
    }

    // ---- epilogue: add bias, store ----
    float b0 = __ldg(bias + colg * 4 + 0);
    float b1 = __ldg(bias + colg * 4 + 1);
    float b2 = __ldg(bias + colg * 4 + 2);
    float b3 = __ldg(bias + colg * 4 + 3);
#pragma unroll
    for (int i = 0; i < 8; i++) {
        int gr = block_row0 + rowg * 8 + i;
        if (gr < N_NODES) {
            float4 o;
            o.x = acc[i][0] + b0;
            o.y = acc[i][1] + b1;
            o.z = acc[i][2] + b2;
            o.w = acc[i][3] + b3;
            *(float4*)(out + (size_t)gr * D + colg * 4) = o;
        }
    }
}

// ---------------------------------------------------------------------------
extern "C" void kernel_launch(void* const* d_in, const int* in_sizes, int n_in,
                              void* d_out, int out_size) {
    const float* x   = (const float*)d_in[0];
    const int*   ei  = (const int*)d_in[1];
    const float* Wl1 = (const float*)d_in[2];
    const float* bl1 = (const float*)d_in[3];
    const float* Wr1 = (const float*)d_in[4];
    const float* Wl2 = (const float*)d_in[5];
    const float* bl2 = (const float*)d_in[6];
    const float* Wr2 = (const float*)d_in[7];
    float* out = (float*)d_out;

    const int* src = ei;
    const int* dst = ei + E_EDGES;

    const int scatter_blocks = (E_EDGES * 32 + 255) / 256;
    const int gemm_blocks = (N_NODES + 63) / 64;

    // degree counts (shared across both layers) + zero accumulator
    zero_s_cnt_kernel<<<512, 256>>>(1);
    count_kernel<<<(E_EDGES + 255) / 256, 256>>>(dst);
    prep_kernel<<<512, 256>>>(Wl1, Wr1, Wl2, Wr2);

    // layer 1
    scatter_kernel<<<scatter_blocks, 256>>>(x, src, dst, 0);
    gemm_kernel<<<gemm_blocks, 256>>>(x, bl1, nullptr, 0);

    // layer 2
    zero_s_cnt_kernel<<<512, 256>>>(0);
    scatter_kernel<<<scatter_blocks, 256>>>(x, src, dst, 1);
    gemm_kernel<<<gemm_blocks, 256>>>(x, bl2, out, 1);
}

// round 4
// speedup vs baseline: 1.1770x; 1.1770x over previous
#include <cuda_runtime.h>
#include <cstddef>

#define N_NODES 50000
#define D 128
#define E_EDGES 800000
#define SCAN_BLK 1024
#define SCAN_NB ((N_NODES + SCAN_BLK - 1) / SCAN_BLK)   // 49

// Scratch (no allocations allowed in kernel_launch)
__device__ float d_agg[(size_t)N_NODES * D];   // scaled mean-aggregated features
__device__ float d_h[(size_t)N_NODES * D];     // layer-1 output
__device__ int   d_deg[N_NODES];
__device__ int   d_rowptr[N_NODES + 1];
__device__ int   d_cursor[N_NODES + 1];
__device__ int   d_adj[E_EDGES];               // src ids grouped by dst
__device__ int   d_bsum[64];
__device__ int   d_boff[64];
__device__ float d_wt1[256 * 128];             // combined [Wl1;Wr1] transposed: wt[k][j]
__device__ float d_wt2[256 * 128];

// ---------------------------------------------------------------------------
__global__ void zero_deg_kernel() {
    int i = blockIdx.x * blockDim.x + threadIdx.x;
    if (i < N_NODES) d_deg[i] = 0;
}

__global__ void count_kernel(const int* __restrict__ dst) {
    int stride = gridDim.x * blockDim.x;
    for (int e = blockIdx.x * blockDim.x + threadIdx.x; e < E_EDGES; e += stride) {
        atomicAdd(&d_deg[dst[e]], 1);
    }
}

// intra-block inclusive scan of deg -> rowptr[i+1]; block sums -> d_bsum
__global__ void scan1_kernel() {
    __shared__ int sh[SCAN_BLK];
    int i = blockIdx.x * SCAN_BLK + threadIdx.x;
    int v = (i < N_NODES) ? d_deg[i] : 0;
    sh[threadIdx.x] = v;
    __syncthreads();
#pragma unroll
    for (int off = 1; off < SCAN_BLK; off <<= 1) {
        int t = (threadIdx.x >= off) ? sh[threadIdx.x - off] : 0;
        __syncthreads();
        sh[threadIdx.x] += t;
        __syncthreads();
    }
    if (i < N_NODES) d_rowptr[i + 1] = sh[threadIdx.x];
    if (threadIdx.x == SCAN_BLK - 1) d_bsum[blockIdx.x] = sh[threadIdx.x];
}

// exclusive scan of the 49 block sums (single block, 64 threads)
__global__ void scan2_kernel() {
    __shared__ int sh[64];
    int t = threadIdx.x;
    int v = (t < SCAN_NB) ? d_bsum[t] : 0;
    sh[t] = v;
    __syncthreads();
#pragma unroll
    for (int off = 1; off < 64; off <<= 1) {
        int u = (t >= off) ? sh[t - off] : 0;
        __syncthreads();
        sh[t] += u;
        __syncthreads();
    }
    d_boff[t] = sh[t] - v;   // exclusive
}

// finalize rowptr and seed fill cursors
__global__ void scan3_kernel() {
    int i = blockIdx.x * blockDim.x + threadIdx.x;
    if (i == 0) { d_rowptr[0] = 0; d_cursor[0] = 0; }
    if (i < N_NODES) {
        int r = d_rowptr[i + 1] + d_boff[i >> 10];
        d_rowptr[i + 1] = r;
        d_cursor[i + 1] = r;
    }
}

__global__ void fill_kernel(const int* __restrict__ src, const int* __restrict__ dst) {
    int stride = gridDim.x * blockDim.x;
    for (int e = blockIdx.x * blockDim.x + threadIdx.x; e < E_EDGES; e += stride) {
        int d = dst[e];
        int p = atomicAdd(&d_cursor[d], 1);
        d_adj[p] = src[e];
    }
}

// Build transposed combined weights wt[k*128+j]:
//   k < 128 : Wl[j*128 + k]   |   k >= 128 : Wr[j*128 + (k-128)]
__global__ void prep_kernel(const float* __restrict__ Wl1, const float* __restrict__ Wr1,
                            const float* __restrict__ Wl2, const float* __restrict__ Wr2) {
    int stride = gridDim.x * blockDim.x;
    for (int i = blockIdx.x * blockDim.x + threadIdx.x; i < 256 * 128; i += stride) {
        int k = i >> 7;
        int j = i & 127;
        if (k < 128) {
            d_wt1[i] = Wl1[j * 128 + k];
            d_wt2[i] = Wl2[j * 128 + k];
        } else {
            d_wt1[i] = Wr1[j * 128 + (k - 128)];
            d_wt2[i] = Wr2[j * 128 + (k - 128)];
        }
    }
}

// One warp per node: sum neighbor rows (float4 per lane), scale by 1/deg, store.
// 2-deep software pipeline keeps >=2 independent L2 loads in flight per lane.
__global__ void __launch_bounds__(256) gather_kernel(const float* __restrict__ x, int layer) {
    const float* __restrict__ xin = (layer == 0) ? x : d_h;
    int gid = blockIdx.x * blockDim.x + threadIdx.x;
    int n = gid >> 5;
    if (n >= N_NODES) return;
    int lane = gid & 31;
    int base = d_rowptr[n];
    int end  = d_rowptr[n + 1];
    int deg  = end - base;

    float4 acc = make_float4(0.f, 0.f, 0.f, 0.f);
    for (int i = base; i < end; i += 32) {
        int cnt = min(32, end - i);
        int sidx = (lane < cnt) ? __ldg(d_adj + i + lane) : 0;
        // prologue: load first row
        int s0 = __shfl_sync(0xffffffffu, sidx, 0);
        float4 v = *(const float4*)(xin + (size_t)s0 * D + lane * 4);
        for (int j = 1; j < cnt; j++) {
            int s = __shfl_sync(0xffffffffu, sidx, j);
            float4 vn = *(const float4*)(xin + (size_t)s * D + lane * 4);
            acc.x += v.x; acc.y += v.y; acc.z += v.z; acc.w += v.w;
            v = vn;
        }
        acc.x += v.x; acc.y += v.y; acc.z += v.z; acc.w += v.w;
    }
    float sc = 1.0f / fmaxf((float)deg, 1.0f);
    acc.x *= sc; acc.y *= sc; acc.z *= sc; acc.w *= sc;
    *(float4*)(d_agg + (size_t)n * D + lane * 4) = acc;
}

// Fused: out[n][j] = sum_{k<128} agg[n][k]*wt[k][j] + sum_{k>=128} xin[n][k-128]*wt[k][j] + b[j]
// SGEMM: BM=128, BN=128, BK=16, 256 threads, 8x8 microtile.
__global__ void __launch_bounds__(256) gemm_kernel(const float* __restrict__ x,
                                                   const float* __restrict__ bias,
                                                   float* __restrict__ outp,
                                                   int layer) {
    const float* __restrict__ wt  = (layer == 0) ? d_wt1 : d_wt2;
    const float* __restrict__ xin = (layer == 0) ? x : d_h;
    float* __restrict__ out       = (layer == 0) ? d_h : outp;

    __shared__ float As[16][132];   // [k][m], pad keeps 16B alignment, breaks conflicts
    __shared__ float Bs[16][128];   // [k][j]

    int tid = threadIdx.x;
    int block_row0 = blockIdx.x * 128;
    int rowg = (tid >> 4) * 8;      // 0,8,...,120
    int colg = (tid & 15) * 8;      // 0,8,...,120

    float acc[8][8];
#pragma unroll
    for (int i = 0; i < 8; i++)
#pragma unroll
        for (int j = 0; j < 8; j++) acc[i][j] = 0.0f;

    for (int kt = 0; kt < 256; kt += 16) {
        const float* __restrict__ asrc = (kt < 128) ? d_agg : xin;
        int kbase = (kt < 128) ? kt : (kt - 128);
        // ---- load A tile (128 rows x 16 k), transpose into As[k][m] ----
#pragma unroll
        for (int p = 0; p < 2; p++) {
            int idx = tid + p * 256;          // 0..511 float4 slots
            int r = idx >> 2;                 // 0..127
            int kq = (idx & 3) * 4;           // 0,4,8,12
            int gr = block_row0 + r;
            int grc = (gr < N_NODES) ? gr : (N_NODES - 1);
            float4 v = *(const float4*)(asrc + (size_t)grc * D + kbase + kq);
            As[kq + 0][r] = v.x;
            As[kq + 1][r] = v.y;
            As[kq + 2][r] = v.z;
            As[kq + 3][r] = v.w;
        }
        // ---- load B tile (16 x 128) ----
#pragma unroll
        for (int p = 0; p < 2; p++) {
            int idx = tid + p * 256;
            int k = idx >> 5;
            int j = (idx & 31) * 4;
            *(float4*)&Bs[k][j] = *(const float4*)(wt + (size_t)(kt + k) * 128 + j);
        }
        __syncthreads();

#pragma unroll
        for (int k = 0; k < 16; k++) {
            float4 a0 = *(const float4*)&As[k][rowg];
            float4 a1 = *(const float4*)&As[k][rowg + 4];
            float4 b0 = *(const float4*)&Bs[k][colg];
            float4 b1 = *(const float4*)&Bs[k][colg + 4];
            float a[8] = {a0.x, a0.y, a0.z, a0.w, a1.x, a1.y, a1.z, a1.w};
            float b[8] = {b0.x, b0.y, b0.z, b0.w, b1.x, b1.y, b1.z, b1.w};
#pragma unroll
            for (int i = 0; i < 8; i++)
#pragma unroll
                for (int j = 0; j < 8; j++)
                    acc[i][j] += a[i] * b[j];
        }
        __syncthreads();
    }

    // ---- epilogue: add bias, store ----
    float bb[8];
#pragma unroll
    for (int j = 0; j < 8; j++) bb[j] = __ldg(bias + colg + j);
#pragma unroll
    for (int i = 0; i < 8; i++) {
        int gr = block_row0 + rowg + i;
        if (gr < N_NODES) {
            float4 o0, o1;
            o0.x = acc[i][0] + bb[0]; o0.y = acc[i][1] + bb[1];
            o0.z = acc[i][2] + bb[2]; o0.w = acc[i][3] + bb[3];
            o1.x = acc[i][4] + bb[4]; o1.y = acc[i][5] + bb[5];
            o1.z = acc[i][6] + bb[6]; o1.w = acc[i][7] + bb[7];
            *(float4*)(out + (size_t)gr * D + colg)     = o0;
            *(float4*)(out + (size_t)gr * D + colg + 4) = o1;
        }
    }
}

// ---------------------------------------------------------------------------
extern "C" void kernel_launch(void* const* d_in, const int* in_sizes, int n_in,
                              void* d_out, int out_size) {
    const float* x   = (const float*)d_in[0];
    const int*   ei  = (const int*)d_in[1];
    const float* Wl1 = (const float*)d_in[2];
    const float* bl1 = (const float*)d_in[3];
    const float* Wr1 = (const float*)d_in[4];
    const float* Wl2 = (const float*)d_in[5];
    const float* bl2 = (const float*)d_in[6];
    const float* Wr2 = (const float*)d_in[7];
    float* out = (float*)d_out;

    const int* src = ei;
    const int* dst = ei + E_EDGES;

    const int gather_blocks = (N_NODES * 32 + 255) / 256;
    const int gemm_blocks   = (N_NODES + 127) / 128;

    // ---- CSR build (shared across both layers) ----
    zero_deg_kernel<<<(N_NODES + 255) / 256, 256>>>();
    count_kernel<<<(E_EDGES + 511) / 512, 256>>>(dst);
    scan1_kernel<<<SCAN_NB, SCAN_BLK>>>();
    scan2_kernel<<<1, 64>>>();
    scan3_kernel<<<(N_NODES + 255) / 256, 256>>>();
    fill_kernel<<<(E_EDGES + 511) / 512, 256>>>(src, dst);
    prep_kernel<<<128, 256>>>(Wl1, Wr1, Wl2, Wr2);

    // ---- layer 1 ----
    gather_kernel<<<gather_blocks, 256>>>(x, 0);
    gemm_kernel<<<gemm_blocks, 256>>>(x, bl1, nullptr, 0);

    // ---- layer 2 ----
    gather_kernel<<<gather_blocks, 256>>>(x, 1);
    gemm_kernel<<<gemm_blocks, 256>>>(x, bl2, out, 1);
}